// round 1
// baseline (speedup 1.0000x reference)
#include <cuda_runtime.h>

#define NFFT 1024
#define NT   256
#define PAD(i) ((i) + ((i) >> 5))

__global__ __launch_bounds__(NT) void ifft1024_kernel(
    const float* __restrict__ re,
    const float* __restrict__ im,
    float* __restrict__ out_r,
    float* __restrict__ out_i)
{
    __shared__ float sr[NFFT + NFFT / 32];
    __shared__ float si[NFFT + NFFT / 32];
    __shared__ float twr[NFFT / 2];
    __shared__ float twi[NFFT / 2];

    const int t = threadIdx.x;
    const long long row = blockIdx.x;

    // Twiddle table: W[k] = exp(+i * 2*pi*k/1024)  (inverse-FFT sign)
    #pragma unroll
    for (int k = t; k < NFFT / 2; k += NT) {
        float s, c;
        sincosf(6.2831853071795864769e0f * (float)k * (1.0f / (float)NFFT), &s, &c);
        twr[k] = c;
        twi[k] = s;
    }

    // Coalesced float4 load, bit-reversed scatter into shared.
    // i0 = 4v has low 2 bits zero, so rev(i0+1)=rev(i0)|512, rev(i0+2)|256, rev(i0+3)|768.
    const float4* r4 = (const float4*)(re + row * NFFT);
    const float4* i4 = (const float4*)(im + row * NFFT);
    #pragma unroll
    for (int v = t; v < NFFT / 4; v += NT) {
        float4 a = r4[v];
        float4 b = i4[v];
        int i0 = v << 2;
        int j0 = (int)(__brev((unsigned)i0) >> 22);
        int j1 = j0 | 512;
        int j2 = j0 | 256;
        int j3 = j0 | 768;
        sr[PAD(j0)] = a.x; sr[PAD(j1)] = a.y; sr[PAD(j2)] = a.z; sr[PAD(j3)] = a.w;
        si[PAD(j0)] = b.x; si[PAD(j1)] = b.y; si[PAD(j2)] = b.z; si[PAD(j3)] = b.w;
    }
    __syncthreads();

    // 10 radix-2 DIT stages. Each butterfly set partitions [0,1024), so the
    // two iterations per thread within a stage are hazard-free.
    #pragma unroll
    for (int h = 1; h < NFFT; h <<= 1) {
        const int twstride = (NFFT / 2) / h;   // W_{2h}^j = table[j * twstride]
        #pragma unroll
        for (int bi = 0; bi < (NFFT / 2) / NT; bi++) {
            int b = t + bi * NT;
            int j = b & (h - 1);
            int k = ((b & ~(h - 1)) << 1) | j;
            float wr = twr[j * twstride];
            float wi = twi[j * twstride];
            int ka = PAD(k);
            int kb = PAD(k + h);
            float xr = sr[kb], xi = si[kb];
            float tr = wr * xr - wi * xi;
            float ti = wr * xi + wi * xr;
            float ur = sr[ka], ui = si[ka];
            sr[ka] = ur + tr;  si[ka] = ui + ti;
            sr[kb] = ur - tr;  si[kb] = ui - ti;
        }
        __syncthreads();
    }

    // Natural-order coalesced float4 stores with 1/N scale.
    const float inv = 1.0f / (float)NFFT;
    float4* or4 = (float4*)(out_r + row * NFFT);
    float4* oi4 = (float4*)(out_i + row * NFFT);
    #pragma unroll
    for (int v = t; v < NFFT / 4; v += NT) {
        int i0 = v << 2;
        float4 a = make_float4(sr[PAD(i0)] * inv, sr[PAD(i0 + 1)] * inv,
                               sr[PAD(i0 + 2)] * inv, sr[PAD(i0 + 3)] * inv);
        float4 b = make_float4(si[PAD(i0)] * inv, si[PAD(i0 + 1)] * inv,
                               si[PAD(i0 + 2)] * inv, si[PAD(i0 + 3)] * inv);
        or4[v] = a;
        oi4[v] = b;
    }
}

extern "C" void kernel_launch(void* const* d_in, const int* in_sizes, int n_in,
                              void* d_out, int out_size)
{
    const float* re = (const float*)d_in[0];
    const float* im = (const float*)d_in[1];
    float* out = (float*)d_out;

    const long long n_elems = (long long)in_sizes[0];     // 8*4096*1024 = 33554432
    const int nrows = (int)(n_elems / NFFT);              // 32768

    float* out_r = out;
    float* out_i = out + n_elems;                         // [yr | yi] layout

    ifft1024_kernel<<<nrows, NT>>>(re, im, out_r, out_i);
}

// round 3
// speedup vs baseline: 1.4603x; 1.4603x over previous
#include <cuda_runtime.h>

#define NFFT 1024
#define NT   256
#define PAD(i) ((i) + ((i) >> 5))

// Fused radix-4 (= 2x radix-2 stages per pass) inverse FFT, 1024 points/CTA.
// Input scattered in FULL bit-reversed order (radix-2 DIT dataflow).
__global__ __launch_bounds__(NT) void ifft1024_r4(
    const float* __restrict__ re,
    const float* __restrict__ im,
    float* __restrict__ out_r,
    float* __restrict__ out_i)
{
    __shared__ float sr[NFFT + NFFT / 32];
    __shared__ float si[NFFT + NFFT / 32];
    __shared__ float twr[NFFT / 2];
    __shared__ float twi[NFFT / 2];

    const int t = threadIdx.x;
    const long long row = blockIdx.x;

    // Twiddle half-table: T[k] = exp(+i * 2*pi*k/1024), k in [0,512)
    #pragma unroll
    for (int k = t; k < NFFT / 2; k += NT) {
        float s, c;
        sincosf(6.2831853071795864769e0f * (float)k * (1.0f / (float)NFFT), &s, &c);
        twr[k] = c;
        twi[k] = s;
    }

    // Coalesced float4 load; FULL bit-reversed scatter into shared.
    // i0 = 4t has low 2 bits zero: rev(i0+1)=rev(i0)|512, rev(i0+2)|256, rev(i0+3)|768.
    {
        const float4* r4 = (const float4*)(re + row * NFFT);
        const float4* i4 = (const float4*)(im + row * NFFT);
        float4 a = r4[t];
        float4 b = i4[t];
        int i0 = t << 2;
        int j0 = (int)(__brev((unsigned)i0) >> 22);
        sr[PAD(j0)]       = a.x;  si[PAD(j0)]       = b.x;
        sr[PAD(j0 | 512)] = a.y;  si[PAD(j0 | 512)] = b.y;
        sr[PAD(j0 | 256)] = a.z;  si[PAD(j0 | 256)] = b.z;
        sr[PAD(j0 | 768)] = a.w;  si[PAD(j0 | 768)] = b.w;
    }
    __syncthreads();

    // ---- Pass 0 (stages h=1 and h=2): twiddles are 1 and i -> pure adds ----
    {
        int k0 = t << 2;
        int p0 = PAD(k0), p1 = PAD(k0 + 1), p2 = PAD(k0 + 2), p3 = PAD(k0 + 3);
        float a0r = sr[p0], a0i = si[p0];
        float a1r = sr[p1], a1i = si[p1];
        float a2r = sr[p2], a2i = si[p2];
        float a3r = sr[p3], a3i = si[p3];
        float u0r = a0r + a1r, u0i = a0i + a1i;
        float u1r = a0r - a1r, u1i = a0i - a1i;
        float u2r = a2r + a3r, u2i = a2i + a3i;
        float u3r = a2r - a3r, u3i = a2i - a3i;
        // y0 = u0 + u2; y2 = u0 - u2; y1 = u1 + i*u3; y3 = u1 - i*u3
        sr[p0] = u0r + u2r;  si[p0] = u0i + u2i;
        sr[p2] = u0r - u2r;  si[p2] = u0i - u2i;
        sr[p1] = u1r - u3i;  si[p1] = u1i + u3r;
        sr[p3] = u1r + u3i;  si[p3] = u1i - u3r;
    }
    __syncthreads();

    // ---- Passes 1..3 (h = 4, 16, 64): fused radix-2 stage pair (h, 2h) ----
    #pragma unroll
    for (int q = 1; q < 4; q++) {
        const int h  = 1 << (2 * q);
        const int j  = t & (h - 1);
        const int k0 = ((t & ~(h - 1)) << 2) + j;
        const int eB = j * (256 / h);          // stage-B exponent, < 256
        const float wBr = twr[eB],     wBi = twi[eB];
        const float wAr = twr[2 * eB], wAi = twi[2 * eB];   // stage-A exponent

        int p0 = PAD(k0), p1 = PAD(k0 + h), p2 = PAD(k0 + 2 * h), p3 = PAD(k0 + 3 * h);
        float a0r = sr[p0], a0i = si[p0];
        float a1r = sr[p1], a1i = si[p1];
        float a2r = sr[p2], a2i = si[p2];
        float a3r = sr[p3], a3i = si[p3];

        // Stage A (half-size h): twiddle wA on both pairs
        float t1r = a1r * wAr - a1i * wAi, t1i = a1r * wAi + a1i * wAr;
        float t3r = a3r * wAr - a3i * wAi, t3i = a3r * wAi + a3i * wAr;
        float u0r = a0r + t1r, u0i = a0i + t1i;
        float u1r = a0r - t1r, u1i = a0i - t1i;
        float u2r = a2r + t3r, u2i = a2i + t3i;
        float u3r = a2r - t3r, u3i = a2i - t3i;

        // Stage B (half-size 2h): (u0,u2) with wB, (u1,u3) with i*wB
        float t2r = u2r * wBr - u2i * wBi, t2i = u2r * wBi + u2i * wBr;
        float t4r = -(u3r * wBi + u3i * wBr), t4i = u3r * wBr - u3i * wBi;

        sr[p0] = u0r + t2r;  si[p0] = u0i + t2i;
        sr[p2] = u0r - t2r;  si[p2] = u0i - t2i;
        sr[p1] = u1r + t4r;  si[p1] = u1i + t4i;
        sr[p3] = u1r - t4r;  si[p3] = u1i - t4i;
        __syncthreads();
    }

    // ---- Pass 4 (h = 256, stages 256 & 512): direct coalesced global store ----
    {
        const int h = 256;
        const float wBr = twr[t],     wBi = twi[t];        // eB = t
        const float wAr = twr[2 * t], wAi = twi[2 * t];

        int p0 = PAD(t), p1 = PAD(t + h), p2 = PAD(t + 2 * h), p3 = PAD(t + 3 * h);
        float a0r = sr[p0], a0i = si[p0];
        float a1r = sr[p1], a1i = si[p1];
        float a2r = sr[p2], a2i = si[p2];
        float a3r = sr[p3], a3i = si[p3];

        float t1r = a1r * wAr - a1i * wAi, t1i = a1r * wAi + a1i * wAr;
        float t3r = a3r * wAr - a3i * wAi, t3i = a3r * wAi + a3i * wAr;
        float u0r = a0r + t1r, u0i = a0i + t1i;
        float u1r = a0r - t1r, u1i = a0i - t1i;
        float u2r = a2r + t3r, u2i = a2i + t3i;
        float u3r = a2r - t3r, u3i = a2i - t3i;

        float t2r = u2r * wBr - u2i * wBi, t2i = u2r * wBi + u2i * wBr;
        float t4r = -(u3r * wBi + u3i * wBr), t4i = u3r * wBr - u3i * wBi;

        const float inv = 1.0f / (float)NFFT;
        float* orow  = out_r + row * NFFT;
        float* oirow = out_i + row * NFFT;
        orow[t]       = (u0r + t2r) * inv;  oirow[t]       = (u0i + t2i) * inv;
        orow[t + 512] = (u0r - t2r) * inv;  oirow[t + 512] = (u0i - t2i) * inv;
        orow[t + 256] = (u1r + t4r) * inv;  oirow[t + 256] = (u1i + t4i) * inv;
        orow[t + 768] = (u1r - t4r) * inv;  oirow[t + 768] = (u1i - t4i) * inv;
    }
}

extern "C" void kernel_launch(void* const* d_in, const int* in_sizes, int n_in,
                              void* d_out, int out_size)
{
    const float* re = (const float*)d_in[0];
    const float* im = (const float*)d_in[1];
    float* out = (float*)d_out;

    const long long n_elems = (long long)in_sizes[0];     // 8*4096*1024
    const int nrows = (int)(n_elems / NFFT);              // 32768

    float* out_r = out;
    float* out_i = out + n_elems;                         // [yr | yi]

    ifft1024_r4<<<nrows, NT>>>(re, im, out_r, out_i);
}

// round 4
// speedup vs baseline: 3.4388x; 2.3548x over previous
#include <cuda_runtime.h>

#define NFFT 1024
#define NT   256
#define WARPS (NT / 32)

// exp(+2*pi*i*k/32), k = 0..15  (inverse-FFT sign)
__device__ const float TW32R[16] = {
    1.00000000f,  0.98078528f,  0.92387953f,  0.83146961f,
    0.70710678f,  0.55557023f,  0.38268343f,  0.19509032f,
    0.00000000f, -0.19509032f, -0.38268343f, -0.55557023f,
   -0.70710678f, -0.83146961f, -0.92387953f, -0.98078528f
};
__device__ const float TW32I[16] = {
    0.00000000f,  0.19509032f,  0.38268343f,  0.55557023f,
    0.70710678f,  0.83146961f,  0.92387953f,  0.98078528f,
    1.00000000f,  0.98078528f,  0.92387953f,  0.83146961f,
    0.70710678f,  0.55557023f,  0.38268343f,  0.19509032f
};

// In-register 32-point inverse DFT (unnormalized), natural in -> natural out.
// Fully unrolled radix-2 DIT; all indices & twiddles are compile-time constants.
__device__ __forceinline__ void fft32_reg(float vr[32], float vi[32])
{
    // bit-reversal (rev5) permutation
    #pragma unroll
    for (int i = 0; i < 32; i++) {
        int j = ((i & 1) << 4) | ((i & 2) << 2) | (i & 4) | ((i & 8) >> 2) | ((i & 16) >> 4);
        if (j > i) {
            float tr = vr[i]; vr[i] = vr[j]; vr[j] = tr;
            float ti = vi[i]; vi[i] = vi[j]; vi[j] = ti;
        }
    }
    #pragma unroll
    for (int h = 1; h < 32; h <<= 1) {
        #pragma unroll
        for (int g = 0; g < 32; g += 2 * h) {
            #pragma unroll
            for (int j = 0; j < h; j++) {
                const float wr = TW32R[j * (16 / h)];
                const float wi = TW32I[j * (16 / h)];
                const int a = g + j, b = g + j + h;
                float tr = vr[b] * wr - vi[b] * wi;
                float ti = vr[b] * wi + vi[b] * wr;
                vr[b] = vr[a] - tr;  vi[b] = vi[a] - ti;
                vr[a] = vr[a] + tr;  vi[a] = vi[a] + ti;
            }
        }
    }
}

// One warp per 1024-pt inverse FFT: 1024 = 32 x 32 Cooley-Tukey.
// Thread L: FFT32 over n2 of x[L + 32*n2]; twiddle W1024^(L*k2); swizzled
// 32x32 transpose via warp-private smem; FFT32 over n1; coalesced store.
__global__ __launch_bounds__(NT, 2) void ifft1024_warp(
    const float* __restrict__ re,
    const float* __restrict__ im,
    float* __restrict__ out_r,
    float* __restrict__ out_i)
{
    __shared__ float tbuf[WARPS][1024];   // 4KB per warp (re, then im, reused)

    const int lane = threadIdx.x & 31;
    const int w    = threadIdx.x >> 5;
    const long long row = (long long)blockIdx.x * WARPS + w;

    const float* xr = re + row * NFFT;
    const float* xi = im + row * NFFT;

    float vr[32], vi[32];

    // Coalesced loads: lanes stride-1, 32 rows apart per register slot.
    #pragma unroll
    for (int n2 = 0; n2 < 32; n2++) {
        vr[n2] = xr[lane + 32 * n2];
        vi[n2] = xi[lane + 32 * n2];
    }

    // Step 1: A[lane, k2] = sum_{n2} W32^{n2 k2} x[lane + 32 n2]
    fft32_reg(vr, vi);

    // Step 2: multiply by W1024^{lane * k2} = exp(+2*pi*i*lane*k2/1024).
    // One exact sincospif for the step; iterate powers (err ~3e-6 << 1e-3).
    {
        float sw, cw;
        sincospif((float)lane * (1.0f / 512.0f), &sw, &cw);
        float wr = 1.0f, wi = 0.0f;
        #pragma unroll
        for (int k2 = 0; k2 < 32; k2++) {
            float br = vr[k2] * wr - vi[k2] * wi;
            float bi = vr[k2] * wi + vi[k2] * wr;
            vr[k2] = br;  vi[k2] = bi;
            float nwr = wr * cw - wi * sw;
            wi = wr * sw + wi * cw;
            wr = nwr;
        }
    }

    // 32x32 transpose through warp-private shared, XOR-swizzled (conflict-free).
    float* buf = tbuf[w];
    #pragma unroll
    for (int k2 = 0; k2 < 32; k2++) buf[lane * 32 + (k2 ^ lane)] = vr[k2];
    __syncwarp();
    #pragma unroll
    for (int n1 = 0; n1 < 32; n1++) vr[n1] = buf[n1 * 32 + (lane ^ n1)];
    __syncwarp();
    #pragma unroll
    for (int k2 = 0; k2 < 32; k2++) buf[lane * 32 + (k2 ^ lane)] = vi[k2];
    __syncwarp();
    #pragma unroll
    for (int n1 = 0; n1 < 32; n1++) vi[n1] = buf[n1 * 32 + (lane ^ n1)];

    // Step 3: X[lane + 32 k1] = sum_{n1} W32^{n1 k1} B[n1, lane]
    fft32_reg(vr, vi);

    // Coalesced scaled stores.
    const float inv = 1.0f / (float)NFFT;
    float* orow  = out_r + row * NFFT;
    float* oirow = out_i + row * NFFT;
    #pragma unroll
    for (int k1 = 0; k1 < 32; k1++) {
        orow[lane + 32 * k1]  = vr[k1] * inv;
        oirow[lane + 32 * k1] = vi[k1] * inv;
    }
}

extern "C" void kernel_launch(void* const* d_in, const int* in_sizes, int n_in,
                              void* d_out, int out_size)
{
    const float* re = (const float*)d_in[0];
    const float* im = (const float*)d_in[1];
    float* out = (float*)d_out;

    const long long n_elems = (long long)in_sizes[0];   // 8*4096*1024
    const int nrows = (int)(n_elems / NFFT);            // 32768

    float* out_r = out;
    float* out_i = out + n_elems;                       // [yr | yi]

    ifft1024_warp<<<nrows / WARPS, NT>>>(re, im, out_r, out_i);
}